// round 2
// baseline (speedup 1.0000x reference)
#include <cuda_runtime.h>

// OU scan: x_i = c_i * x_{i-1} + sqrt(1-c_i^2) * z_i, c_i = exp(-theta*dt_i), x_{-1} = x0
// Single-pass decoupled-lookback scan over S, one thread per d-channel, L steps per block.

#define THETA 0.5f

constexpr int B = 64;
constexpr int S = 4096;
constexpr int D = 256;
constexpr int L = 32;          // timesteps per block
constexpr int K = S / L;       // 128 chunks per batch row
constexpr int NC = B * K;      // 8192 chunks total

// Scratch (no allocs allowed): chunk state for decoupled lookback.
__device__ int   g_flags[NC];          // 0 = none, 1 = aggregate ready, 2 = inclusive ready
__device__ float g_aggA[NC];           // per-chunk product of c (d-independent)
__device__ float g_aggB[(long)NC * D]; // per-chunk local scan end value (from zero state)
__device__ float g_incX[(long)NC * D]; // inclusive prefix state after chunk

__global__ void reset_flags_kernel() {
    int i = blockIdx.x * blockDim.x + threadIdx.x;
    if (i < NC) g_flags[i] = 0;
}

__global__ __launch_bounds__(256) void ou_scan_kernel(
    const float* __restrict__ t,    // [B,S]
    const float* __restrict__ x0,   // [B,D]
    const float* __restrict__ z,    // [B,S,D]
    float* __restrict__ out)        // [B,S,D]
{
    const int k = blockIdx.x;       // chunk index (fastest-varying bid -> predecessor launched first)
    const int b = blockIdx.y;
    const int d = threadIdx.x;
    const int s0 = k * L;

    // --- per-chunk coefficients (d-independent): c, w = sqrt(1-c^2) ---
    __shared__ float cs[L], ws[L];
    if (threadIdx.x < L) {
        int s = s0 + threadIdx.x;
        float tc = t[b * S + s];
        float tp = (s == 0) ? 0.0f : t[b * S + s - 1];
        float dt = tc - tp;
        float c  = expf(-THETA * dt);
        cs[threadIdx.x] = c;
        ws[threadIdx.x] = sqrtf(fmaxf(1.0f - c * c, 0.0f));
    }
    __syncthreads();

    // --- batch-load z chunk into registers (MLP = L) ---
    float v[L];
    const float* zp = z + ((long)b * S + s0) * D + d;
#pragma unroll
    for (int j = 0; j < L; j++) v[j] = zp[(long)j * D];

    // --- local scan from zero state; A = product of c over chunk ---
    float x = 0.0f, A = 1.0f;
#pragma unroll
    for (int j = 0; j < L; j++) {
        x = fmaf(cs[j], x, ws[j] * v[j]);
        v[j] = x;
        A *= cs[j];
    }

    // --- publish aggregate (A, B[d]) ---
    const int cidx = b * K + k;
    g_aggB[(long)cidx * D + d] = x;
    if (d == 0) g_aggA[cidx] = A;
    __threadfence();
    __syncthreads();
    if (d == 0) atomicExch(&g_flags[cidx], 1);

    // --- decoupled lookback: compute exclusive prefix state xprev for channel d ---
    float accA = 1.0f, accB = 0.0f, xprev;
    int j2 = k - 1;
    while (true) {
        if (j2 < 0) {               // reached the start: apply accumulated map to x0
            xprev = fmaf(accA, x0[b * D + d], accB);
            break;
        }
        volatile int* vf = &g_flags[b * K + j2];
        int f = *vf;
        int spins = 0;
        while (f == 0) {
            if (++spins > 4) __nanosleep(20);
            f = *vf;
        }
        __threadfence();
        if (f == 2) {
            xprev = fmaf(accA, g_incX[(long)(b * K + j2) * D + d], accB);
            break;
        }
        // aggregate only: fold chunk j2 under the maps accumulated so far
        accB = fmaf(accA, g_aggB[(long)(b * K + j2) * D + d], accB);
        accA *= g_aggA[b * K + j2];
        j2--;
    }

    // --- publish inclusive prefix for this chunk ---
    float xinc = fmaf(A, xprev, x);
    g_incX[(long)cidx * D + d] = xinc;
    __threadfence();
    __syncthreads();
    if (d == 0) atomicExch(&g_flags[cidx], 2);

    // --- fixup and stream output: x_true[j] = x_local[j] + (prod_{i<=j} c_i) * xprev ---
    float cp = 1.0f;
    float* op = out + ((long)b * S + s0) * D + d;
#pragma unroll
    for (int j = 0; j < L; j++) {
        cp *= cs[j];
        op[(long)j * D] = fmaf(cp, xprev, v[j]);
    }
}

extern "C" void kernel_launch(void* const* d_in, const int* in_sizes, int n_in,
                              void* d_out, int out_size)
{
    const float* t  = (const float*)d_in[0];   // [B,S,1]
    const float* x0 = (const float*)d_in[1];   // [B,1,D]
    const float* z  = (const float*)d_in[2];   // [B,S,D]
    float* out = (float*)d_out;                // [B,S,D]

    reset_flags_kernel<<<(NC + 255) / 256, 256>>>();
    dim3 grid(K, B);
    ou_scan_kernel<<<grid, 256>>>(t, x0, z, out);
}

// round 5
// speedup vs baseline: 1.8444x; 1.8444x over previous
#include <cuda_runtime.h>

// OU scan: x_i = c_i * x_{i-1} + sqrt(1-c_i^2) * z_i, c_i = exp(-theta*dt_i), x_{-1} = x0
// Single-pass decoupled-lookback scan, batch-fastest grid (shallow lookback),
// acquire-load flag polls, L2-direct aggregate reads, streaming cache hints.

#define THETA 0.5f

constexpr int B = 64;
constexpr int S = 4096;
constexpr int D = 256;
constexpr int L = 32;          // timesteps per chunk
constexpr int K = S / L;       // 128 chunks per batch row
constexpr int NC = B * K;      // 8192 chunks total

// Scratch (no allocs allowed): chunk state for decoupled lookback.
__device__ int   g_flags[NC];          // 0 = none, 1 = aggregate ready, 2 = inclusive ready
__device__ float g_aggA[NC];           // per-chunk product of c (d-independent)
__device__ float g_aggB[(long)NC * D]; // per-chunk local scan end value (from zero state)
__device__ float g_incX[(long)NC * D]; // inclusive prefix state after chunk

__global__ void reset_flags_kernel() {
    int i = blockIdx.x * blockDim.x + threadIdx.x;
    if (i < NC) g_flags[i] = 0;
}

__device__ __forceinline__ int ld_flag_acquire(const int* p) {
    int v;
    asm volatile("ld.acquire.gpu.global.b32 %0, [%1];" : "=r"(v) : "l"(p) : "memory");
    return v;
}
__device__ __forceinline__ float ld_cg_f32(const float* p) {
    float v;
    asm volatile("ld.global.cg.f32 %0, [%1];" : "=f"(v) : "l"(p));
    return v;
}

__global__ __launch_bounds__(256) void ou_scan_kernel(
    const float* __restrict__ t,    // [B,S]
    const float* __restrict__ x0,   // [B,D]
    const float* __restrict__ z,    // [B,S,D]
    float* __restrict__ out)        // [B,S,D]
{
    const int b = blockIdx.x;       // batch fastest -> concurrent chunks spread across rows
    const int k = blockIdx.y;       // chunk index; predecessor (b,k-1) has smaller bid
    const int d = threadIdx.x;
    const int s0 = k * L;
    const int cidx = b * K + k;

    // --- per-chunk coefficients (d-independent): c, w = sqrt(1-c^2) ---
    __shared__ float cs[L], ws[L];
    if (threadIdx.x < L) {
        int s = s0 + threadIdx.x;
        float tc = t[b * S + s];
        float tp = (s == 0) ? 0.0f : t[b * S + s - 1];
        float c  = expf(-THETA * (tc - tp));
        cs[threadIdx.x] = c;
        ws[threadIdx.x] = sqrtf(fmaxf(1.0f - c * c, 0.0f));
    }
    __syncthreads();

    // --- batch-load z chunk into registers (MLP = L), streaming hint ---
    float v[L];
    const float* zp = z + ((long)b * S + s0) * D + d;
#pragma unroll
    for (int j = 0; j < L; j++) v[j] = __ldcs(zp + (long)j * D);

    // --- local scan from zero state; A = product of c over chunk ---
    float x = 0.0f, A = 1.0f;
#pragma unroll
    for (int j = 0; j < L; j++) {
        x = fmaf(cs[j], x, ws[j] * v[j]);
        v[j] = x;
        A *= cs[j];
    }

    // --- resolve exclusive prefix state xprev ---
    float xprev;
    if (k == 0) {
        xprev = x0[b * D + d];      // no lookback; will publish f=2 directly below
    } else {
        // publish aggregate (A, B[d]) so successors can make progress
        g_aggB[(long)cidx * D + d] = x;
        if (d == 0) g_aggA[cidx] = A;
        __threadfence();            // all threads: release writes to GPU scope
        __syncthreads();
        if (d == 0) atomicExch(&g_flags[cidx], 1);

        float accA = 1.0f, accB = 0.0f;
        int j = k - 1;
        while (true) {
            const int* fp = &g_flags[b * K + j];
            int f = ld_flag_acquire(fp);
            int spins = 0;
            while (f == 0) {
                if (++spins > 8) __nanosleep(64);
                f = ld_flag_acquire(fp);
            }
            long base = (long)(b * K + j) * D + d;
            if (f == 2) {
                xprev = fmaf(accA, ld_cg_f32(&g_incX[base]), accB);
                break;
            }
            // aggregate only: fold chunk j under accumulated map
            accB = fmaf(accA, ld_cg_f32(&g_aggB[base]), accB);
            accA *= ld_cg_f32(&g_aggA[b * K + j]);
            if (--j < 0) {          // reached row start
                xprev = fmaf(accA, x0[b * D + d], accB);
                break;
            }
        }
    }

    // --- publish inclusive prefix (not needed for the last chunk of a row) ---
    if (k < K - 1) {
        g_incX[(long)cidx * D + d] = fmaf(A, xprev, x);
        __threadfence();
        __syncthreads();
        if (d == 0) atomicExch(&g_flags[cidx], 2);
    }

    // --- fixup and stream output: x_true[j] = x_local[j] + (prod_{i<=j} c_i) * xprev ---
    float cp = 1.0f;
    float* op = out + ((long)b * S + s0) * D + d;
#pragma unroll
    for (int j = 0; j < L; j++) {
        cp *= cs[j];
        __stcs(op + (long)j * D, fmaf(cp, xprev, v[j]));
    }
}

extern "C" void kernel_launch(void* const* d_in, const int* in_sizes, int n_in,
                              void* d_out, int out_size)
{
    const float* t  = (const float*)d_in[0];   // [B,S,1]
    const float* x0 = (const float*)d_in[1];   // [B,1,D]
    const float* z  = (const float*)d_in[2];   // [B,S,D]
    float* out = (float*)d_out;                // [B,S,D]

    reset_flags_kernel<<<(NC + 255) / 256, 256>>>();
    dim3 grid(B, K);                           // batch fastest, chunks outer
    ou_scan_kernel<<<grid, 256>>>(t, x0, z, out);
}

// round 11
// speedup vs baseline: 2.0771x; 1.1261x over previous
#include <cuda_runtime.h>

// OU scan: x_i = c_i * x_{i-1} + sqrt(1-c_i^2) * z_i, c_i = exp(-theta*dt_i), x_{-1} = x0
// PERSISTENT design: one CTA per (batch row, d-half). Each CTA scans the full
// S=4096 sequence serially in 32-step tiles, state carried in registers.
// ZERO inter-block synchronization, zero scratch, one kernel, one z read.
// All 4096 (c, w) coefficients precomputed into smem once per CTA.
// Explicit double-buffering overlaps next-tile loads with current-tile scan+store.

#define THETA 0.5f

constexpr int B = 64;
constexpr int S = 4096;
constexpr int D = 256;
constexpr int TILE = 32;            // timesteps per tile
constexpr int NT = S / TILE;        // 128 tiles
constexpr int DH = 128;             // channels per CTA (half of D)

__global__ __launch_bounds__(DH) void ou_persist_kernel(
    const float* __restrict__ t,    // [B,S]
    const float* __restrict__ x0,   // [B,D]
    const float* __restrict__ z,    // [B,S,D]
    float* __restrict__ out)        // [B,S,D]
{
    const int q = blockIdx.x;              // 0/1 -> which half of D
    const int b = blockIdx.y;
    const int d = q * DH + threadIdx.x;    // global channel

    // --- precompute all coefficients for this row into smem (once) ---
    __shared__ float scs[S];               // c_s
    __shared__ float sws[S];               // sqrt(1 - c_s^2)
    {
        const float* tr = t + b * S;
#pragma unroll
        for (int i = 0; i < S / DH; i++) {       // 32 iterations
            int s = i * DH + threadIdx.x;
            float tc = tr[s];
            float tp = (s == 0) ? 0.0f : tr[s - 1];
            float c  = expf(-THETA * (tc - tp));
            scs[s] = c;
            sws[s] = sqrtf(fmaxf(1.0f - c * c, 0.0f));
        }
    }
    __syncthreads();                        // only barrier in the kernel

    const long base = (long)b * S * D + d;
    const float* zp = z + base;
    float* op = out + base;

    float xs = x0[b * D + d];               // running state (register-resident)

    float va[TILE], vb[TILE];

    // prolog: load tile 0
#pragma unroll
    for (int j = 0; j < TILE; j++) va[j] = __ldcs(zp + (long)j * D);

    // main loop, manually unrolled x2 for double buffering:
    // loads of the NEXT tile are issued before the scan of the CURRENT tile.
#pragma unroll 1
    for (int tile = 0; tile < NT; tile += 2) {
        // prefetch tile+1 into vb (tile <= 126 so tile+1 < 128 always)
        {
            const float* p = zp + (long)(tile + 1) * TILE * D;
#pragma unroll
            for (int j = 0; j < TILE; j++) vb[j] = __ldcs(p + (long)j * D);
        }
        // scan + store tile (from va)
        {
            const int s0 = tile * TILE;
            float* o = op + (long)s0 * D;
#pragma unroll
            for (int j = 0; j < TILE; j++) {
                xs = fmaf(scs[s0 + j], xs, sws[s0 + j] * va[j]);
                __stcs(o + (long)j * D, xs);
            }
        }
        // prefetch tile+2 into va (skip on last pair)
        if (tile + 2 < NT) {
            const float* p = zp + (long)(tile + 2) * TILE * D;
#pragma unroll
            for (int j = 0; j < TILE; j++) va[j] = __ldcs(p + (long)j * D);
        }
        // scan + store tile+1 (from vb)
        {
            const int s0 = (tile + 1) * TILE;
            float* o = op + (long)s0 * D;
#pragma unroll
            for (int j = 0; j < TILE; j++) {
                xs = fmaf(scs[s0 + j], xs, sws[s0 + j] * vb[j]);
                __stcs(o + (long)j * D, xs);
            }
        }
    }
}

extern "C" void kernel_launch(void* const* d_in, const int* in_sizes, int n_in,
                              void* d_out, int out_size)
{
    const float* t  = (const float*)d_in[0];   // [B,S,1]
    const float* x0 = (const float*)d_in[1];   // [B,1,D]
    const float* z  = (const float*)d_in[2];   // [B,S,D]
    float* out = (float*)d_out;                // [B,S,D]

    dim3 grid(2, B);                           // 128 CTAs: (d-half, batch)
    ou_persist_kernel<<<grid, DH>>>(t, x0, z, out);
}